// round 2
// baseline (speedup 1.0000x reference)
#include <cuda_runtime.h>
#include <math.h>

// Problem constants
#define HH   2048   // hidden size
#define IMOE 1408   // moe intermediate
#define NE   8      // routed experts
#define TT   2048   // tokens (B*S)
#define ISH  2816   // shared intermediate
#define TOPK 2

// ---------------- scratch (__device__ globals; no runtime alloc) -------------
__device__ int   g_cnt[NE];
__device__ int   g_rows[NE * TT];          // token id per (expert, slot)
__device__ int   g_tok2row[TT * TOPK];     // global row (= e*TT + slot) for token's k-th pick
__device__ float g_wt[TT * TOPK];          // combine weight for token's k-th pick
__device__ float g_act  [(size_t)NE * TT * IMOE];  // routed silu(g)*u   (~92 MB)
__device__ float g_y    [(size_t)NE * TT * HH];    // routed down out    (~128 MB)
__device__ float g_act_s[(size_t)TT * ISH];        // shared silu(g)*u   (~23 MB)
__device__ float g_ys   [(size_t)TT * HH];         // shared down out    (~16 MB)

__global__ void zero_cnt_kernel() {
    if (threadIdx.x < NE) g_cnt[threadIdx.x] = 0;
}

// ---------------- router: one warp per token --------------------------------
__global__ void router_kernel(const float* __restrict__ x,
                              const float* __restrict__ rw,
                              const float* __restrict__ bias) {
    int t    = (blockIdx.x * blockDim.x + threadIdx.x) >> 5;
    int lane = threadIdx.x & 31;
    if (t >= TT) return;
    const float* xt = x + (size_t)t * HH;

    float logits[NE];
#pragma unroll
    for (int e = 0; e < NE; e++) {
        const float* w = rw + e * HH;
        float s = 0.f;
        for (int h = lane; h < HH; h += 32) s = fmaf(xt[h], w[h], s);
#pragma unroll
        for (int o = 16; o; o >>= 1) s += __shfl_xor_sync(0xffffffffu, s, o);
        logits[e] = s;
    }
    if (lane != 0) return;

    float scores[NE], sfc[NE];
#pragma unroll
    for (int e = 0; e < NE; e++) {
        scores[e] = 1.f / (1.f + expf(-logits[e]));
        sfc[e]    = scores[e] + bias[e];
    }
    // group scores: NG=4 groups of E/NG=2 -> top-2 of 2 == sum of both
    float gs[4];
#pragma unroll
    for (int g = 0; g < 4; g++) gs[g] = sfc[2 * g] + sfc[2 * g + 1];
    // top-2 groups (ties -> lower index, matching lax.top_k)
    int g0 = 0;
#pragma unroll
    for (int g = 1; g < 4; g++) if (gs[g] > gs[g0]) g0 = g;
    int g1 = -1;
#pragma unroll
    for (int g = 0; g < 4; g++) {
        if (g == g0) continue;
        if (g1 < 0 || gs[g] > gs[g1]) g1 = g;
    }
    // top-2 experts among masked sfc (masked-out = 0.0; sigmoid > 0 so candidates win)
    int i0 = -1; float v0 = -1.f;
#pragma unroll
    for (int e = 0; e < NE; e++) {
        int g = e >> 1;
        float v = (g == g0 || g == g1) ? sfc[e] : 0.0f;
        if (v > v0) { v0 = v; i0 = e; }
    }
    int i1 = -1; float v1 = -1.f;
#pragma unroll
    for (int e = 0; e < NE; e++) {
        if (e == i0) continue;
        int g = e >> 1;
        float v = (g == g0 || g == g1) ? sfc[e] : 0.0f;
        if (v > v1) { v1 = v; i1 = e; }
    }
    float w0 = scores[i0], w1 = scores[i1];
    float inv = 2.5f / (w0 + w1 + 1e-20f);
    w0 *= inv; w1 *= inv;

    int p0 = atomicAdd(&g_cnt[i0], 1);
    g_rows[i0 * TT + p0]   = t;
    g_tok2row[t * 2 + 0]   = i0 * TT + p0;
    g_wt[t * 2 + 0]        = w0;
    int p1 = atomicAdd(&g_cnt[i1], 1);
    g_rows[i1 * TT + p1]   = t;
    g_tok2row[t * 2 + 1]   = i1 * TT + p1;
    g_wt[t * 2 + 1]        = w1;
}

// ---------------- fused gate+up GEMM (NT) with SiLU*up epilogue --------------
// C[m][n] = silu(sum_k A[m][k]*Wg[n][k]) * (sum_k A[m][k]*Wu[n][k])
// 64x64 tile, BK=16, 256 threads, 4x4 per thread, dual accumulators.
template <int N, int K, bool ROUTED>
__global__ __launch_bounds__(256)
void gemm_gateup_k(const float* __restrict__ Xin,
                   const float* __restrict__ Wg_all,
                   const float* __restrict__ Wu_all) {
    const int e  = blockIdx.z;
    const int M  = ROUTED ? g_cnt[e] : TT;
    const int m0 = blockIdx.y * 64;
    if (m0 >= M) return;
    const int n0 = blockIdx.x * 64;

    const int*   rl  = ROUTED ? (g_rows + e * TT) : nullptr;
    const float* wg  = Wg_all + (size_t)e * N * K;
    const float* wu  = Wu_all + (size_t)e * N * K;
    float*       out = ROUTED ? (g_act + (size_t)e * TT * IMOE) : g_act_s;

    __shared__ float As[16][64];
    __shared__ float Bg[16][64];
    __shared__ float Bu[16][64];

    const int tid = threadIdx.x;
    const int tx  = tid & 15;       // n sub-tile
    const int ty  = tid >> 4;       // m sub-tile
    const int lr  = tid >> 2;       // 0..63 row-within-tile (loader)
    const int lk  = (tid & 3) * 4;  // 0,4,8,12 (loader k offset)

    const int arow = m0 + lr;
    const float* aptr = nullptr;
    if (arow < M) {
        int grow = ROUTED ? rl[arow] : arow;
        aptr = Xin + (size_t)grow * K;
    }
    const float* bgptr = wg + (size_t)(n0 + lr) * K;
    const float* buptr = wu + (size_t)(n0 + lr) * K;

    float accg[4][4], accu[4][4];
#pragma unroll
    for (int i = 0; i < 4; i++)
#pragma unroll
        for (int j = 0; j < 4; j++) { accg[i][j] = 0.f; accu[i][j] = 0.f; }

    for (int k0 = 0; k0 < K; k0 += 16) {
        float4 av = aptr ? *reinterpret_cast<const float4*>(aptr + k0 + lk)
                         : make_float4(0.f, 0.f, 0.f, 0.f);
        float4 gv = *reinterpret_cast<const float4*>(bgptr + k0 + lk);
        float4 uv = *reinterpret_cast<const float4*>(buptr + k0 + lk);
        As[lk + 0][lr] = av.x; As[lk + 1][lr] = av.y;
        As[lk + 2][lr] = av.z; As[lk + 3][lr] = av.w;
        Bg[lk + 0][lr] = gv.x; Bg[lk + 1][lr] = gv.y;
        Bg[lk + 2][lr] = gv.z; Bg[lk + 3][lr] = gv.w;
        Bu[lk + 0][lr] = uv.x; Bu[lk + 1][lr] = uv.y;
        Bu[lk + 2][lr] = uv.z; Bu[lk + 3][lr] = uv.w;
        __syncthreads();
#pragma unroll
        for (int kk = 0; kk < 16; kk++) {
            float4 a4 = *reinterpret_cast<const float4*>(&As[kk][ty * 4]);
            float4 g4 = *reinterpret_cast<const float4*>(&Bg[kk][tx * 4]);
            float4 u4 = *reinterpret_cast<const float4*>(&Bu[kk][tx * 4]);
            float a[4] = {a4.x, a4.y, a4.z, a4.w};
            float g[4] = {g4.x, g4.y, g4.z, g4.w};
            float u[4] = {u4.x, u4.y, u4.z, u4.w};
#pragma unroll
            for (int i = 0; i < 4; i++)
#pragma unroll
                for (int j = 0; j < 4; j++) {
                    accg[i][j] = fmaf(a[i], g[j], accg[i][j]);
                    accu[i][j] = fmaf(a[i], u[j], accu[i][j]);
                }
        }
        __syncthreads();
    }

#pragma unroll
    for (int i = 0; i < 4; i++) {
        int r = m0 + ty * 4 + i;
        if (r >= M) continue;
#pragma unroll
        for (int j = 0; j < 4; j++) {
            float gvv = accg[i][j];
            float act = gvv / (1.f + expf(-gvv)) * accu[i][j];
            out[(size_t)r * N + n0 + tx * 4 + j] = act;
        }
    }
}

// ---------------- down GEMM (NT) ---------------------------------------------
template <int N, int K, bool ROUTED>
__global__ __launch_bounds__(256)
void gemm_down_k(const float* __restrict__ W_all) {
    const int e  = blockIdx.z;
    const int M  = ROUTED ? g_cnt[e] : TT;
    const int m0 = blockIdx.y * 64;
    if (m0 >= M) return;
    const int n0 = blockIdx.x * 64;

    const float* Xin = ROUTED ? (g_act + (size_t)e * TT * IMOE) : g_act_s;
    const float* w   = W_all + (size_t)e * N * K;
    float*       out = ROUTED ? (g_y + (size_t)e * TT * HH) : g_ys;

    __shared__ float As[16][64];
    __shared__ float Bs[16][64];

    const int tid = threadIdx.x;
    const int tx  = tid & 15;
    const int ty  = tid >> 4;
    const int lr  = tid >> 2;
    const int lk  = (tid & 3) * 4;

    const int arow = m0 + lr;
    const float* aptr = (arow < M) ? (Xin + (size_t)arow * K) : nullptr;
    const float* bptr = w + (size_t)(n0 + lr) * K;

    float acc[4][4];
#pragma unroll
    for (int i = 0; i < 4; i++)
#pragma unroll
        for (int j = 0; j < 4; j++) acc[i][j] = 0.f;

    for (int k0 = 0; k0 < K; k0 += 16) {
        float4 av = aptr ? *reinterpret_cast<const float4*>(aptr + k0 + lk)
                         : make_float4(0.f, 0.f, 0.f, 0.f);
        float4 bv = *reinterpret_cast<const float4*>(bptr + k0 + lk);
        As[lk + 0][lr] = av.x; As[lk + 1][lr] = av.y;
        As[lk + 2][lr] = av.z; As[lk + 3][lr] = av.w;
        Bs[lk + 0][lr] = bv.x; Bs[lk + 1][lr] = bv.y;
        Bs[lk + 2][lr] = bv.z; Bs[lk + 3][lr] = bv.w;
        __syncthreads();
#pragma unroll
        for (int kk = 0; kk < 16; kk++) {
            float4 a4 = *reinterpret_cast<const float4*>(&As[kk][ty * 4]);
            float4 b4 = *reinterpret_cast<const float4*>(&Bs[kk][tx * 4]);
            float a[4] = {a4.x, a4.y, a4.z, a4.w};
            float b[4] = {b4.x, b4.y, b4.z, b4.w};
#pragma unroll
            for (int i = 0; i < 4; i++)
#pragma unroll
                for (int j = 0; j < 4; j++)
                    acc[i][j] = fmaf(a[i], b[j], acc[i][j]);
        }
        __syncthreads();
    }

#pragma unroll
    for (int i = 0; i < 4; i++) {
        int r = m0 + ty * 4 + i;
        if (r >= M) continue;
#pragma unroll
        for (int j = 0; j < 4; j++)
            out[(size_t)r * N + n0 + tx * 4 + j] = acc[i][j];
    }
}

// ---------------- combine: out = w0*y0 + w1*y1 + shared ----------------------
__global__ void combine_kernel(float* __restrict__ out) {
    int idx = blockIdx.x * blockDim.x + threadIdx.x;
    if (idx >= TT * HH) return;
    int t = idx >> 11;             // / HH
    int h = idx & (HH - 1);
    int   r0 = g_tok2row[2 * t];
    int   r1 = g_tok2row[2 * t + 1];
    float w0 = g_wt[2 * t];
    float w1 = g_wt[2 * t + 1];
    float v  = w0 * g_y[(size_t)r0 * HH + h];
    v       += w1 * g_y[(size_t)r1 * HH + h];
    v       += g_ys[idx];
    out[idx] = v;
}

// ---------------- launch ------------------------------------------------------
extern "C" void kernel_launch(void* const* d_in, const int* in_sizes, int n_in,
                              void* d_out, int out_size) {
    const float* x    = (const float*)d_in[0];
    const float* rw   = (const float*)d_in[1];
    const float* bias = (const float*)d_in[2];
    const float* gw   = (const float*)d_in[3];
    const float* uw   = (const float*)d_in[4];
    const float* dw   = (const float*)d_in[5];
    const float* sgw  = (const float*)d_in[6];
    const float* suw  = (const float*)d_in[7];
    const float* sdw  = (const float*)d_in[8];
    float* out = (float*)d_out;

    zero_cnt_kernel<<<1, 32>>>();
    router_kernel<<<TT / 8, 256>>>(x, rw, bias);

    // routed gate+up: per expert, M<=T, N=1408, K=2048
    gemm_gateup_k<IMOE, HH, true><<<dim3(IMOE / 64, TT / 64, NE), 256>>>(x, gw, uw);
    // routed down: N=2048, K=1408
    gemm_down_k<HH, IMOE, true><<<dim3(HH / 64, TT / 64, NE), 256>>>(dw);
    // shared gate+up: M=T, N=2816, K=2048
    gemm_gateup_k<ISH, HH, false><<<dim3(ISH / 64, TT / 64, 1), 256>>>(x, sgw, suw);
    // shared down: N=2048, K=2816
    gemm_down_k<HH, ISH, false><<<dim3(HH / 64, TT / 64, 1), 256>>>(sdw);

    combine_kernel<<<(TT * HH + 255) / 256, 256>>>(out);
}

// round 5
// speedup vs baseline: 2.0292x; 2.0292x over previous
#include <cuda_runtime.h>
#include <cuda_bf16.h>
#include <math.h>
#include <stdint.h>

#define HH   2048
#define IMOE 1408
#define NE   8
#define TT   2048
#define ISH  2816

// ---------------- scratch (__device__ globals) ----------------
__device__ int   g_cnt[NE];
__device__ int   g_rows[NE * TT];
__device__ int   g_tok2row[TT * 2];
__device__ float g_wt[TT * 2];
__device__ float g_gate  [(size_t)NE * TT * IMOE];
__device__ float g_act   [(size_t)NE * TT * IMOE];
__device__ float g_y     [(size_t)NE * TT * HH];
__device__ float g_gate_s[(size_t)TT * ISH];
__device__ float g_act_s [(size_t)TT * ISH];
__device__ float g_ys    [(size_t)TT * HH];

// ---------------- helpers ----------------
__device__ __forceinline__ uint32_t smem_u32(const void* p) {
    uint32_t a;
    asm("{ .reg .u64 t; cvta.to.shared.u64 t, %1; cvt.u32.u64 %0, t; }"
        : "=r"(a) : "l"(p));
    return a;
}

__device__ __forceinline__ void ldsm4(uint32_t* r, uint32_t addr) {
    asm volatile("ldmatrix.sync.aligned.m8n8.x4.shared.b16 {%0,%1,%2,%3}, [%4];"
                 : "=r"(r[0]), "=r"(r[1]), "=r"(r[2]), "=r"(r[3]) : "r"(addr));
}

__device__ __forceinline__ void mma16816(float* d, const uint32_t* a,
                                         uint32_t b0, uint32_t b1) {
    asm volatile("mma.sync.aligned.m16n8k16.row.col.f32.bf16.bf16.f32 "
                 "{%0,%1,%2,%3}, {%4,%5,%6,%7}, {%8,%9}, {%0,%1,%2,%3};"
                 : "+f"(d[0]), "+f"(d[1]), "+f"(d[2]), "+f"(d[3])
                 : "r"(a[0]), "r"(a[1]), "r"(a[2]), "r"(a[3]), "r"(b0), "r"(b1));
}

__device__ __forceinline__ void split2(float x, float y, uint32_t& hi, uint32_t& lo) {
    __nv_bfloat16 hx = __float2bfloat16_rn(x);
    __nv_bfloat16 hy = __float2bfloat16_rn(y);
    __nv_bfloat16 lx = __float2bfloat16_rn(x - __bfloat162float(hx));
    __nv_bfloat16 ly = __float2bfloat16_rn(y - __bfloat162float(hy));
    __nv_bfloat162 H(hx, hy), L(lx, ly);
    hi = *reinterpret_cast<uint32_t*>(&H);
    lo = *reinterpret_cast<uint32_t*>(&L);
}

#define STSV4(addr, a, b, c, d) \
    asm volatile("st.shared.v4.b32 [%0], {%1,%2,%3,%4};" \
                 :: "r"(addr), "r"(a), "r"(b), "r"(c), "r"(d) : "memory")

// smem tile geometry: 128 rows x 32 bf16, padded to 40 bf16 (80B) per row
#define ROWB   80
#define MATB   10240          // 128 * 80
#define STAGEB (4 * MATB)     // Ahi, Alo, Bhi, Blo
#define SMEM_SZ (2 * STAGEB)  // double buffered = 81920

// ---------------- misc kernels ----------------
__global__ void zero_cnt_kernel() {
    if (threadIdx.x < NE) g_cnt[threadIdx.x] = 0;
}

__global__ void router_kernel(const float* __restrict__ x,
                              const float* __restrict__ rw,
                              const float* __restrict__ bias) {
    int t    = (blockIdx.x * blockDim.x + threadIdx.x) >> 5;
    int lane = threadIdx.x & 31;
    if (t >= TT) return;
    const float* xt = x + (size_t)t * HH;

    float logits[NE];
#pragma unroll
    for (int e = 0; e < NE; e++) {
        const float* w = rw + e * HH;
        float s = 0.f;
        for (int h = lane; h < HH; h += 32) s = fmaf(xt[h], w[h], s);
#pragma unroll
        for (int o = 16; o; o >>= 1) s += __shfl_xor_sync(0xffffffffu, s, o);
        logits[e] = s;
    }
    if (lane != 0) return;

    float scores[NE], sfc[NE];
#pragma unroll
    for (int e = 0; e < NE; e++) {
        scores[e] = 1.f / (1.f + expf(-logits[e]));
        sfc[e]    = scores[e] + bias[e];
    }
    float gs[4];
#pragma unroll
    for (int g = 0; g < 4; g++) gs[g] = sfc[2 * g] + sfc[2 * g + 1];
    int g0 = 0;
#pragma unroll
    for (int g = 1; g < 4; g++) if (gs[g] > gs[g0]) g0 = g;
    int g1 = -1;
#pragma unroll
    for (int g = 0; g < 4; g++) {
        if (g == g0) continue;
        if (g1 < 0 || gs[g] > gs[g1]) g1 = g;
    }
    int i0 = -1; float v0 = -1.f;
#pragma unroll
    for (int e = 0; e < NE; e++) {
        int g = e >> 1;
        float v = (g == g0 || g == g1) ? sfc[e] : 0.0f;
        if (v > v0) { v0 = v; i0 = e; }
    }
    int i1 = -1; float v1 = -1.f;
#pragma unroll
    for (int e = 0; e < NE; e++) {
        if (e == i0) continue;
        int g = e >> 1;
        float v = (g == g0 || g == g1) ? sfc[e] : 0.0f;
        if (v > v1) { v1 = v; i1 = e; }
    }
    float w0 = scores[i0], w1 = scores[i1];
    float inv = 2.5f / (w0 + w1 + 1e-20f);
    w0 *= inv; w1 *= inv;

    int p0 = atomicAdd(&g_cnt[i0], 1);
    g_rows[i0 * TT + p0] = t;
    g_tok2row[t * 2 + 0] = i0 * TT + p0;
    g_wt[t * 2 + 0]      = w0;
    int p1 = atomicAdd(&g_cnt[i1], 1);
    g_rows[i1 * TT + p1] = t;
    g_tok2row[t * 2 + 1] = i1 * TT + p1;
    g_wt[t * 2 + 1]      = w1;
}

// ---------------- split-bf16 HMMA GEMM: D[M,N] = A[M,K] @ B[N,K]^T ----------------
// 128x128 CTA tile, BK=32 (fp32 in gmem -> hi/lo bf16 in smem), 8 warps (4m x 2n),
// warp tile 32x64, mma.sync m16n8k16, 3 combos (HH, HL, LH).
template <int N, int K, bool ROUTED, bool GATHER, bool SILU_EPI>
__global__ __launch_bounds__(256, 1)
void hmma_gemm(const float* __restrict__ A,
               const float* __restrict__ B,
               const float* __restrict__ AUX,   // gate result for silu epilogue
               float* __restrict__ D) {
    extern __shared__ __align__(128) char smem[];
    const int e  = blockIdx.z;
    const int M  = ROUTED ? g_cnt[e] : TT;
    const int m0 = blockIdx.y * 128;
    if (m0 >= M) return;
    const int n0   = blockIdx.x * 128;
    const int tid  = threadIdx.x;
    const int lane = tid & 31;
    const int wid  = tid >> 5;
    const int wm   = wid & 3;      // 4 m-slices of 32
    const int wn   = wid >> 2;     // 2 n-slices of 64
    const uint32_t sb0 = smem_u32(smem);

    // ---- loader mapping: 2 threads per tile row, 16 fp32 each ----
    const int lr   = tid >> 1;            // 0..127
    const int colf = (tid & 1) * 16;      // 0 / 16
    const float* arow = nullptr;
    {
        int row = m0 + lr;
        if (row < M) {
            size_t gr = GATHER ? (size_t)g_rows[e * TT + row]
                               : (ROUTED ? (size_t)e * TT + row : (size_t)row);
            arow = A + gr * (size_t)K + colf;
        }
    }
    const float* brow = B + (ROUTED ? (size_t)e * N * K : 0)
                          + (size_t)(n0 + lr) * K + colf;
    const uint32_t stsoff = (uint32_t)lr * ROWB + (uint32_t)colf * 2;

    float acc[2][8][4];
#pragma unroll
    for (int f = 0; f < 2; f++)
#pragma unroll
        for (int j = 0; j < 8; j++)
#pragma unroll
            for (int q = 0; q < 4; q++) acc[f][j][q] = 0.f;

    const int NCH = K / 32;
    float4 pa[4], pb[4];

    // prefetch + store chunk 0 into stage 0
#pragma unroll
    for (int i = 0; i < 4; i++) {
        pa[i] = arow ? *((const float4*)arow + i) : make_float4(0.f, 0.f, 0.f, 0.f);
        pb[i] = *((const float4*)brow + i);
    }
    {
        uint32_t h[8], l[8], bh[8], bl[8];
#pragma unroll
        for (int i = 0; i < 4; i++) {
            split2(pa[i].x, pa[i].y, h[2 * i], l[2 * i]);
            split2(pa[i].z, pa[i].w, h[2 * i + 1], l[2 * i + 1]);
            split2(pb[i].x, pb[i].y, bh[2 * i], bl[2 * i]);
            split2(pb[i].z, pb[i].w, bh[2 * i + 1], bl[2 * i + 1]);
        }
        uint32_t sa = sb0 + stsoff;
        STSV4(sa,              h[0], h[1], h[2], h[3]);
        STSV4(sa + 16,         h[4], h[5], h[6], h[7]);
        STSV4(sa + MATB,       l[0], l[1], l[2], l[3]);
        STSV4(sa + MATB + 16,  l[4], l[5], l[6], l[7]);
        STSV4(sa + 2 * MATB,      bh[0], bh[1], bh[2], bh[3]);
        STSV4(sa + 2 * MATB + 16, bh[4], bh[5], bh[6], bh[7]);
        STSV4(sa + 3 * MATB,      bl[0], bl[1], bl[2], bl[3]);
        STSV4(sa + 3 * MATB + 16, bl[4], bl[5], bl[6], bl[7]);
    }
    __syncthreads();

    for (int c = 0; c < NCH; c++) {
        const int s = c & 1;
        // prefetch next chunk
        if (c + 1 < NCH) {
#pragma unroll
            for (int i = 0; i < 4; i++) {
                pa[i] = arow ? *((const float4*)(arow + (c + 1) * 32) + i)
                             : make_float4(0.f, 0.f, 0.f, 0.f);
                pb[i] = *((const float4*)(brow + (c + 1) * 32) + i);
            }
        }
        // compute stage s
        const uint32_t stg = sb0 + (uint32_t)s * STAGEB;
#pragma unroll
        for (int ks = 0; ks < 2; ks++) {
            const uint32_t acol = (uint32_t)(ks * 16 + (lane >> 4) * 8) * 2;
            uint32_t aH[2][4], aL[2][4];
#pragma unroll
            for (int f = 0; f < 2; f++) {
                uint32_t ra = (uint32_t)(wm * 32 + f * 16 + (lane & 15)) * ROWB + acol;
                ldsm4(aH[f], stg + ra);
                ldsm4(aL[f], stg + MATB + ra);
            }
            uint32_t bH[8][2], bL[8][2];
#pragma unroll
            for (int nb = 0; nb < 4; nb++) {
                uint32_t rb = (uint32_t)(wn * 64 + nb * 16 + (lane & 15)) * ROWB + acol;
                uint32_t r4[4];
                ldsm4(r4, stg + 2 * MATB + rb);
                bH[2 * nb][0] = r4[0]; bH[2 * nb][1] = r4[2];
                bH[2 * nb + 1][0] = r4[1]; bH[2 * nb + 1][1] = r4[3];
                ldsm4(r4, stg + 3 * MATB + rb);
                bL[2 * nb][0] = r4[0]; bL[2 * nb][1] = r4[2];
                bL[2 * nb + 1][0] = r4[1]; bL[2 * nb + 1][1] = r4[3];
            }
#pragma unroll
            for (int f = 0; f < 2; f++)
#pragma unroll
                for (int j = 0; j < 8; j++) {
                    mma16816(acc[f][j], aH[f], bH[j][0], bH[j][1]);
                    mma16816(acc[f][j], aH[f], bL[j][0], bL[j][1]);
                    mma16816(acc[f][j], aL[f], bH[j][0], bH[j][1]);
                }
        }
        // store next chunk into stage s^1
        if (c + 1 < NCH) {
            uint32_t h[8], l[8], bh[8], bl[8];
#pragma unroll
            for (int i = 0; i < 4; i++) {
                split2(pa[i].x, pa[i].y, h[2 * i], l[2 * i]);
                split2(pa[i].z, pa[i].w, h[2 * i + 1], l[2 * i + 1]);
                split2(pb[i].x, pb[i].y, bh[2 * i], bl[2 * i]);
                split2(pb[i].z, pb[i].w, bh[2 * i + 1], bl[2 * i + 1]);
            }
            uint32_t sa = sb0 + (uint32_t)(s ^ 1) * STAGEB + stsoff;
            STSV4(sa,              h[0], h[1], h[2], h[3]);
            STSV4(sa + 16,         h[4], h[5], h[6], h[7]);
            STSV4(sa + MATB,       l[0], l[1], l[2], l[3]);
            STSV4(sa + MATB + 16,  l[4], l[5], l[6], l[7]);
            STSV4(sa + 2 * MATB,      bh[0], bh[1], bh[2], bh[3]);
            STSV4(sa + 2 * MATB + 16, bh[4], bh[5], bh[6], bh[7]);
            STSV4(sa + 3 * MATB,      bl[0], bl[1], bl[2], bl[3]);
            STSV4(sa + 3 * MATB + 16, bl[4], bl[5], bl[6], bl[7]);
        }
        __syncthreads();
    }

    // ---- epilogue ----
    const size_t rowbase = ROUTED ? (size_t)e * TT : 0;
#pragma unroll
    for (int f = 0; f < 2; f++) {
#pragma unroll
        for (int half = 0; half < 2; half++) {
            int rloc = m0 + wm * 32 + f * 16 + (lane >> 2) + half * 8;
            if (rloc >= M) continue;
            size_t rg = rowbase + rloc;
#pragma unroll
            for (int j = 0; j < 8; j++) {
                int cg = n0 + wn * 64 + j * 8 + (lane & 3) * 2;
                float vx = acc[f][j][half * 2 + 0];
                float vy = acc[f][j][half * 2 + 1];
                if (SILU_EPI) {
                    float2 gv = *(const float2*)(AUX + rg * N + cg);
                    vx = gv.x / (1.f + expf(-gv.x)) * vx;
                    vy = gv.y / (1.f + expf(-gv.y)) * vy;
                }
                float2 o = make_float2(vx, vy);
                *(float2*)(D + rg * N + cg) = o;
            }
        }
    }
}

// ---------------- combine ----------------
__global__ void combine_kernel(float4* __restrict__ out) {
    int idx = blockIdx.x * blockDim.x + threadIdx.x;
    if (idx >= TT * HH / 4) return;
    int t  = idx >> 9;
    int h4 = idx & 511;
    float w0 = g_wt[2 * t], w1 = g_wt[2 * t + 1];
    float4 a = *((const float4*)(g_y + (size_t)g_tok2row[2 * t]     * HH) + h4);
    float4 b = *((const float4*)(g_y + (size_t)g_tok2row[2 * t + 1] * HH) + h4);
    float4 c = *((const float4*)g_ys + idx);
    float4 o;
    o.x = fmaf(w0, a.x, fmaf(w1, b.x, c.x));
    o.y = fmaf(w0, a.y, fmaf(w1, b.y, c.y));
    o.z = fmaf(w0, a.z, fmaf(w1, b.z, c.z));
    o.w = fmaf(w0, a.w, fmaf(w1, b.w, c.w));
    out[idx] = o;
}

// ---------------- launch ----------------
extern "C" void kernel_launch(void* const* d_in, const int* in_sizes, int n_in,
                              void* d_out, int out_size) {
    const float* x    = (const float*)d_in[0];
    const float* rw   = (const float*)d_in[1];
    const float* bias = (const float*)d_in[2];
    const float* gw   = (const float*)d_in[3];
    const float* uw   = (const float*)d_in[4];
    const float* dw   = (const float*)d_in[5];
    const float* sgw  = (const float*)d_in[6];
    const float* suw  = (const float*)d_in[7];
    const float* sdw  = (const float*)d_in[8];
    float* out = (float*)d_out;

    float *p_gate, *p_act, *p_y, *p_gate_s, *p_act_s, *p_ys;
    cudaGetSymbolAddress((void**)&p_gate,   g_gate);
    cudaGetSymbolAddress((void**)&p_act,    g_act);
    cudaGetSymbolAddress((void**)&p_y,      g_y);
    cudaGetSymbolAddress((void**)&p_gate_s, g_gate_s);
    cudaGetSymbolAddress((void**)&p_act_s,  g_act_s);
    cudaGetSymbolAddress((void**)&p_ys,     g_ys);

    cudaFuncSetAttribute(hmma_gemm<IMOE, HH, true,  true,  false>, cudaFuncAttributeMaxDynamicSharedMemorySize, SMEM_SZ);
    cudaFuncSetAttribute(hmma_gemm<IMOE, HH, true,  true,  true >, cudaFuncAttributeMaxDynamicSharedMemorySize, SMEM_SZ);
    cudaFuncSetAttribute(hmma_gemm<HH, IMOE, true,  false, false>, cudaFuncAttributeMaxDynamicSharedMemorySize, SMEM_SZ);
    cudaFuncSetAttribute(hmma_gemm<ISH,  HH, false, false, false>, cudaFuncAttributeMaxDynamicSharedMemorySize, SMEM_SZ);
    cudaFuncSetAttribute(hmma_gemm<ISH,  HH, false, false, true >, cudaFuncAttributeMaxDynamicSharedMemorySize, SMEM_SZ);
    cudaFuncSetAttribute(hmma_gemm<HH,  ISH, false, false, false>, cudaFuncAttributeMaxDynamicSharedMemorySize, SMEM_SZ);

    zero_cnt_kernel<<<1, 32>>>();
    router_kernel<<<TT / 8, 256>>>(x, rw, bias);

    // routed: gate -> up(silu epi) -> down
    hmma_gemm<IMOE, HH, true, true, false><<<dim3(IMOE / 128, TT / 128, NE), 256, SMEM_SZ>>>(x, gw, nullptr, p_gate);
    hmma_gemm<IMOE, HH, true, true, true ><<<dim3(IMOE / 128, TT / 128, NE), 256, SMEM_SZ>>>(x, uw, p_gate, p_act);
    hmma_gemm<HH, IMOE, true, false, false><<<dim3(HH / 128, TT / 128, NE), 256, SMEM_SZ>>>(p_act, dw, nullptr, p_y);

    // shared expert
    hmma_gemm<ISH, HH, false, false, false><<<dim3(ISH / 128, TT / 128, 1), 256, SMEM_SZ>>>(x, sgw, nullptr, p_gate_s);
    hmma_gemm<ISH, HH, false, false, true ><<<dim3(ISH / 128, TT / 128, 1), 256, SMEM_SZ>>>(x, suw, p_gate_s, p_act_s);
    hmma_gemm<HH, ISH, false, false, false><<<dim3(HH / 128, TT / 128, 1), 256, SMEM_SZ>>>(p_act_s, sdw, nullptr, p_ys);

    combine_kernel<<<(TT * HH / 4 + 255) / 256, 256>>>((float4*)out);
}